// round 2
// baseline (speedup 1.0000x reference)
#include <cuda_runtime.h>

// PseudoLevinsonDurbinRecursion: B=65536 batches, each solves a 64x64 symmetric
// Toeplitz system via Levinson-Durbin (O(M^2) per batch, exact same solution as
// linalg.solve for SPD Toeplitz). Output per batch: [K, a1..a64] with
// K = sqrt(E_M) (final prediction error == r0 + r1.a).
//
// One thread per batch. a[] fully register-resident via complete unroll of the
// triangular recursion. r[] staged in shared (stride-65 rows -> conflict-free,
// 65 mod 32 == 1). Coalesced global load/store through the same shared buffer.

constexpr int M  = 64;
constexpr int NR = M + 1;   // 65 floats per row
constexpr int BT = 128;     // threads (= batches) per block

__global__ __launch_bounds__(BT)
void levdur_kernel(const float* __restrict__ g_r,
                   float* __restrict__ g_out,
                   int nbatch)
{
    __shared__ float sm[BT * NR];   // 33,280 B
    const int tid = threadIdx.x;
    const long long base  = (long long)blockIdx.x * BT * NR;
    const long long total = (long long)nbatch * NR;

    // Coalesced load: flat copy of this block's 128 rows.
    #pragma unroll
    for (int i = 0; i < NR; ++i) {
        long long idx = base + (long long)i * BT + tid;
        if (idx < total) sm[i * BT + tid] = g_r[idx];
    }
    __syncthreads();

    const int batch = blockIdx.x * BT + tid;
    float* r = &sm[tid * NR];   // this thread's private row (no cross-thread use)

    if (batch < nbatch) {
        float a[NR];            // a[1..M] live in registers (constant indices)
        float E = r[0];

        #pragma unroll
        for (int m = 1; m <= M; ++m) {
            // acc = r[m] + sum_{j=1}^{m-1} a[j] * r[m-j], 2-way split to
            // break the FFMA dependency chain.
            float acc0 = r[m];
            float acc1 = 0.0f;
            #pragma unroll
            for (int j = 1; j + 1 <= m - 1; j += 2) {
                acc0 = fmaf(a[j],     r[m - j],     acc0);
                acc1 = fmaf(a[j + 1], r[m - j - 1], acc1);
            }
            if (((m - 1) & 1) != 0) {            // leftover term j = m-1 (m even)
                acc0 = fmaf(a[m - 1], r[1], acc0);
            }

            float k = __fdividef(-(acc0 + acc1), E);
            E = fmaf(-k * k, E, E);              // E *= (1 - k^2)

            // a_new[j] = a[j] + k * a[m-j], done as symmetric pairs in place.
            #pragma unroll
            for (int i = 1; i < m - i; ++i) {
                float t = a[i];
                a[i]     = fmaf(k, a[m - i], t);
                a[m - i] = fmaf(k, t, a[m - i]);
            }
            if ((m & 1) == 0 && m >= 2) {        // self-paired middle element
                int h = m >> 1;
                a[h] = fmaf(k, a[h], a[h]);
            }
            a[m] = k;
        }

        // K = sqrt(E_M); overwrite our shared row with the result.
        r[0] = sqrtf(E);
        #pragma unroll
        for (int i = 1; i <= M; ++i) r[i] = a[i];
    }
    __syncthreads();

    // Coalesced store.
    #pragma unroll
    for (int i = 0; i < NR; ++i) {
        long long idx = base + (long long)i * BT + tid;
        if (idx < total) g_out[idx] = sm[i * BT + tid];
    }
}

extern "C" void kernel_launch(void* const* d_in, const int* in_sizes, int n_in,
                              void* d_out, int out_size)
{
    const float* r = (const float*)d_in[0];
    float* out = (float*)d_out;
    int nbatch = in_sizes[0] / NR;           // 65536
    int grid = (nbatch + BT - 1) / BT;       // 512
    levdur_kernel<<<grid, BT>>>(r, out, nbatch);
}